// round 14
// baseline (speedup 1.0000x reference)
#include <cuda_runtime.h>
#include <cuda_fp16.h>
#include <cstdint>

#define BB   8
#define NN   2048
#define FIN  256
#define DD   128
#define LEAK 0.2f

// Scratch (device globals — no allocation in kernel_launch)
__device__ __half g_Hh[BB * NN * DD];   // H_ in fp16, [16384, 128]
__device__ float  g_f1[BB * NN];
__device__ float  g_f2[BB * NN];

// ---------------------------------------------------------------------------
// PTX helpers
// ---------------------------------------------------------------------------
__device__ __forceinline__ void cp_async16(uint32_t smem_addr, const void* gptr)
{
    asm volatile("cp.async.cg.shared.global [%0], [%1], 16;"
                 :: "r"(smem_addr), "l"(gptr));
}
__device__ __forceinline__ void cp_commit() { asm volatile("cp.async.commit_group;"); }
__device__ __forceinline__ void cp_wait1()  { asm volatile("cp.async.wait_group 1;"); }

__device__ __forceinline__ void ldm_x4(uint32_t& r0, uint32_t& r1, uint32_t& r2, uint32_t& r3,
                                       uint32_t addr)
{
    asm volatile("ldmatrix.sync.aligned.m8n8.x4.shared.b16 {%0,%1,%2,%3}, [%4];"
                 : "=r"(r0), "=r"(r1), "=r"(r2), "=r"(r3)
                 : "r"(addr));
}
__device__ __forceinline__ void ldm_x4_t(uint32_t& r0, uint32_t& r1, uint32_t& r2, uint32_t& r3,
                                         uint32_t addr)
{
    asm volatile("ldmatrix.sync.aligned.m8n8.x4.trans.shared.b16 {%0,%1,%2,%3}, [%4];"
                 : "=r"(r0), "=r"(r1), "=r"(r2), "=r"(r3)
                 : "r"(addr));
}
__device__ __forceinline__ void mma16816(float* c, uint32_t a0, uint32_t a1, uint32_t a2,
                                         uint32_t a3, uint32_t b0, uint32_t b1)
{
    asm volatile(
        "mma.sync.aligned.m16n8k16.row.col.f32.f16.f16.f32 "
        "{%0,%1,%2,%3}, {%4,%5,%6,%7}, {%8,%9}, {%0,%1,%2,%3};"
        : "+f"(c[0]), "+f"(c[1]), "+f"(c[2]), "+f"(c[3])
        : "r"(a0), "r"(a1), "r"(a2), "r"(a3), "r"(b0), "r"(b1));
}

__device__ __forceinline__ void split2(float x, float y, uint32_t& hi, uint32_t& lo)
{
    __half hx = __float2half_rn(x), hy = __float2half_rn(y);
    __half2 h = __halves2half2(hx, hy);
    __half2 l = __floats2half2_rn(x - __half2float(hx), y - __half2float(hy));
    hi = *(uint32_t*)&h;
    lo = *(uint32_t*)&l;
}

// ---------------------------------------------------------------------------
// Kernel 1 (v2): H_ = H @ W via fp16 tensor cores with 3-term hi/lo split
// (fp32-accurate: Hhi*Whi + Hhi*Wlo + Hlo*Whi, fp32 accumulate).
// CTA = 64 rows, 512 threads (16 warps: mq=w>>2 m16-band, nq=w&3 n32-slice),
// grid 256. K loop: 8 chunks of k32, reg-prefetch 1 ahead, 1 barrier/iter.
// Epilogue: fp16 H_ -> g_Hh, fused f1/f2 row-dots -> g_f1/g_f2.
// smem: hAhi[2][64][32] 8K | hAlo 8K | hWhi[2][32][128] 16K | hWlo 16K |
//       sPart1/2 2K  => 51200 B
// ---------------------------------------------------------------------------
#define PJ_OAHI 0u
#define PJ_OALO 8192u
#define PJ_OWHI 16384u
#define PJ_OWLO 32768u
#define PJ_OPRT 49152u
#define PJ_SMEM 51200

__global__ __launch_bounds__(512, 2) void proj_kernel(
    const float* __restrict__ H, const float* __restrict__ W,
    const float* __restrict__ a1, const float* __restrict__ a2)
{
    extern __shared__ char sm[];
    const uint32_t base = (uint32_t)__cvta_generic_to_shared(sm);
    float* sPart1 = (float*)(sm + PJ_OPRT);           // [64][4]
    float* sPart2 = (float*)(sm + PJ_OPRT + 1024);    // [64][4]

    const int tid  = threadIdx.x;
    const int lane = tid & 31;
    const int w    = tid >> 5;
    const int row0 = blockIdx.x * 64;                 // flat row base (0..16383)

    // load mappings
    const int hRow = tid >> 2,  hSeg = tid & 3;       // tid<256: H rows 0..63
    const int wRow = tid >> 4,  wSeg = tid & 15;      // W k-rows 0..31

    const uint32_t stAoff = (uint32_t)(hRow * 64 + ((hSeg ^ ((hRow >> 1) & 3)) << 4));
    const uint32_t stWoff = (uint32_t)(wRow * 256 + ((wSeg ^ (wRow & 7)) << 4));

    float4 ha0, ha1, wa0, wa1;
    auto loadH = [&](int kc) {
        const float4* p = (const float4*)(H + (size_t)(row0 + hRow) * FIN + kc * 32 + hSeg * 8);
        ha0 = p[0]; ha1 = p[1];
    };
    auto loadW = [&](int kc) {
        const float4* p = (const float4*)(W + (size_t)(kc * 32 + wRow) * DD + wSeg * 8);
        wa0 = p[0]; wa1 = p[1];
    };

    // mma addressing
    const int mq = w >> 2;              // 0..3 : rows mq*16..mq*16+15
    const int nq = w & 3;               // 0..3 : cols nq*32..nq*32+31
    const int l15 = lane & 15;
    const int hi  = lane >> 4;
    uint32_t aOff[2], bOff[2][2];
#pragma unroll
    for (int ksel = 0; ksel < 2; ksel++) {
        int arow = mq * 16 + l15;
        aOff[ksel] = (uint32_t)(arow * 64 + (((ksel * 2 + hi) ^ ((arow >> 1) & 3)) << 4));
        int brow = ksel * 16 + l15;
#pragma unroll
        for (int ns = 0; ns < 2; ns++)
            bOff[ksel][ns] = (uint32_t)(brow * 256 +
                (((nq * 4 + ns * 2 + hi) ^ (brow & 7)) << 4));
    }

    float acc[4][4];
#pragma unroll
    for (int f = 0; f < 4; f++)
#pragma unroll
        for (int c = 0; c < 4; c++) acc[f][c] = 0.f;

    if (tid < 256) loadH(0);
    loadW(0);

    for (int kc = 0; kc < 8; kc++) {
        const uint32_t abuf = (uint32_t)(kc & 1) * 4096u;
        const uint32_t wbuf = (uint32_t)(kc & 1) * 8192u;

        // convert & store hi/lo fp16 (generic-pointer 16B stores)
        if (tid < 256) {
            uint32_t h0, l0, h1, l1, h2, l2, h3, l3;
            split2(ha0.x, ha0.y, h0, l0); split2(ha0.z, ha0.w, h1, l1);
            split2(ha1.x, ha1.y, h2, l2); split2(ha1.z, ha1.w, h3, l3);
            *(uint4*)(sm + PJ_OAHI + abuf + stAoff) = make_uint4(h0, h1, h2, h3);
            *(uint4*)(sm + PJ_OALO + abuf + stAoff) = make_uint4(l0, l1, l2, l3);
        }
        {
            uint32_t h0, l0, h1, l1, h2, l2, h3, l3;
            split2(wa0.x, wa0.y, h0, l0); split2(wa0.z, wa0.w, h1, l1);
            split2(wa1.x, wa1.y, h2, l2); split2(wa1.z, wa1.w, h3, l3);
            *(uint4*)(sm + PJ_OWHI + wbuf + stWoff) = make_uint4(h0, h1, h2, h3);
            *(uint4*)(sm + PJ_OWLO + wbuf + stWoff) = make_uint4(l0, l1, l2, l3);
        }
        if (kc < 7) {
            if (tid < 256) loadH(kc + 1);
            loadW(kc + 1);
        }
        __syncthreads();

        // 3-split MMA on buf[kc&1]
        const uint32_t ahiB = base + PJ_OAHI + abuf;
        const uint32_t aloB = base + PJ_OALO + abuf;
        const uint32_t whiB = base + PJ_OWHI + wbuf;
        const uint32_t wloB = base + PJ_OWLO + wbuf;
#pragma unroll
        for (int ksel = 0; ksel < 2; ksel++) {
            uint32_t ah0, ah1, ah2, ah3, al0, al1, al2, al3;
            ldm_x4(ah0, ah1, ah2, ah3, ahiB + aOff[ksel]);
            ldm_x4(al0, al1, al2, al3, aloB + aOff[ksel]);
#pragma unroll
            for (int ns = 0; ns < 2; ns++) {
                uint32_t bh0, bh1, bh2, bh3, bl0, bl1, bl2, bl3;
                ldm_x4_t(bh0, bh1, bh2, bh3, whiB + bOff[ksel][ns]);
                ldm_x4_t(bl0, bl1, bl2, bl3, wloB + bOff[ksel][ns]);
                mma16816(acc[ns * 2 + 0], ah0, ah1, ah2, ah3, bh0, bh1);
                mma16816(acc[ns * 2 + 1], ah0, ah1, ah2, ah3, bh2, bh3);
                mma16816(acc[ns * 2 + 0], ah0, ah1, ah2, ah3, bl0, bl1);
                mma16816(acc[ns * 2 + 1], ah0, ah1, ah2, ah3, bl2, bl3);
                mma16816(acc[ns * 2 + 0], al0, al1, al2, al3, bh0, bh1);
                mma16816(acc[ns * 2 + 1], al0, al1, al2, al3, bh2, bh3);
            }
        }
    }

    // ---- epilogue ----
    const int gid = lane >> 2;
    const int tig = lane & 3;

    // f1/f2 partials over this lane's 8 columns
    float p1[2] = {0.f, 0.f}, p2[2] = {0.f, 0.f};
#pragma unroll
    for (int f = 0; f < 4; f++) {
        int col = nq * 32 + (f >> 1) * 16 + (f & 1) * 8 + tig * 2;
        float a1x = a1[col], a1y = a1[col + 1];
        float a2x = a2[col], a2y = a2[col + 1];
        p1[0] += acc[f][0] * a1x + acc[f][1] * a1y;
        p1[1] += acc[f][2] * a1x + acc[f][3] * a1y;
        p2[0] += acc[f][0] * a2x + acc[f][1] * a2y;
        p2[1] += acc[f][2] * a2x + acc[f][3] * a2y;
    }
#pragma unroll
    for (int off = 1; off <= 2; off <<= 1) {
#pragma unroll
        for (int rh = 0; rh < 2; rh++) {
            p1[rh] += __shfl_xor_sync(0xffffffffu, p1[rh], off);
            p2[rh] += __shfl_xor_sync(0xffffffffu, p2[rh], off);
        }
    }
    if (tig == 0) {
#pragma unroll
        for (int rh = 0; rh < 2; rh++) {
            int r = mq * 16 + rh * 8 + gid;
            sPart1[r * 4 + nq] = p1[rh];
            sPart2[r * 4 + nq] = p2[rh];
        }
    }

    // fp16 H_ store
#pragma unroll
    for (int rh = 0; rh < 2; rh++) {
        size_t grow = (size_t)(row0 + mq * 16 + rh * 8 + gid) * DD;
#pragma unroll
        for (int f = 0; f < 4; f++) {
            int col = nq * 32 + (f >> 1) * 16 + (f & 1) * 8 + tig * 2;
            __half2 hv = __floats2half2_rn(acc[f][rh * 2 + 0], acc[f][rh * 2 + 1]);
            *(uint32_t*)(&g_Hh[grow + col]) = *(uint32_t*)&hv;
        }
    }
    __syncthreads();

    if (tid < 64) {
        float s1 = sPart1[tid * 4] + sPart1[tid * 4 + 1] + sPart1[tid * 4 + 2] + sPart1[tid * 4 + 3];
        float s2 = sPart2[tid * 4] + sPart2[tid * 4 + 1] + sPart2[tid * 4 + 2] + sPart2[tid * 4 + 3];
        g_f1[row0 + tid] = s1;
        g_f2[row0 + tid] = s2;
    }
}

// ---------------------------------------------------------------------------
// Kernel 2: fused attention — EXACT R7 version (benched 64.4 us).
// ---------------------------------------------------------------------------
#define T_TILES   (NN / 64)
#define SA_STRIDE 16384u
#define SH_STRIDE 16384u
#define SP_STRIDE 8192u
#define OFF_SA    0u
#define OFF_SH    49152u
#define OFF_SP    98304u
#define OFF_SZ    114688u
#define SMEM_MAIN 114944

__global__ __launch_bounds__(512, 2) void gat_main_kernel(
    const float* __restrict__ A, float* __restrict__ out)
{
    extern __shared__ char smem[];
    const uint32_t smBase = (uint32_t)__cvta_generic_to_shared(smem);
    const uint32_t saBase = smBase + OFF_SA;
    const uint32_t shBase = smBase + OFF_SH;
    const uint32_t spBase = smBase + OFF_SP;
    float* sZ = (float*)(smem + OFF_SZ);

    const int tid  = threadIdx.x;
    const int lane = tid & 31;
    const int w    = tid >> 5;          // 0..15
    const int b    = blockIdx.y;
    const int i0   = blockIdx.x * 64;

    const float*  Ab  = A + (size_t)b * NN * NN;
    const __half* Hhb = g_Hh + (size_t)b * NN * DD;

    // A(t): WARP-SELF copy of the 4 rows this warp exp-reads.
    const int aRowSelf = 4 * w + (lane >> 4);
    const int aChunk   = lane & 15;
    auto issueA = [&](int t) {
        if (t >= T_TILES) return;
        const uint32_t dbuf = saBase + (uint32_t)(t % 3) * SA_STRIDE;
        const int j0 = t * 64;
#pragma unroll
        for (int p = 0; p < 2; p++) {
            int row = aRowSelf + p * 2;
            cp_async16(dbuf + (uint32_t)(row * 256 + aChunk * 16),
                       Ab + (size_t)(i0 + row) * NN + j0 + aChunk * 4);
        }
    };
    // H(t): spread copy, consumed post-barrier. XOR-chunk swizzle.
    const int ldRow = tid >> 4;
    const int ldC16 = tid & 15;
    auto issueH = [&](int t) {
        if (t >= T_TILES) return;
        const uint32_t dbuf = shBase + (uint32_t)(t % 3) * SH_STRIDE;
        const int j0 = t * 64;
#pragma unroll
        for (int p = 0; p < 2; p++) {
            int row = ldRow + p * 32;
            int sw = ldC16 ^ (row & 7);
            cp_async16(dbuf + (uint32_t)(row * 256 + sw * 16),
                       Hhb + (size_t)(j0 + row) * DD + ldC16 * 8);
        }
    };

    float rf1[4];
#pragma unroll
    for (int r = 0; r < 4; r++) rf1[r] = g_f1[b * NN + i0 + w * 4 + r];

    float zacc[4] = {0.f, 0.f, 0.f, 0.f};
    float acc[4][4];
#pragma unroll
    for (int nb = 0; nb < 4; nb++)
#pragma unroll
        for (int c = 0; c < 4; c++) acc[nb][c] = 0.f;

    const int mb = w & 3;
    const int nq = w >> 2;

    const int aRow  = mb * 16 + (lane & 15);
    const int bRowL = lane & 15;
    const int hi    = lane >> 4;
    uint32_t aOff[4];
#pragma unroll
    for (int ks = 0; ks < 4; ks++)
        aOff[ks] = (uint32_t)(aRow * 128 + (((ks * 2 + hi) ^ (aRow & 7)) << 4));
    uint32_t bOff[4][2];
#pragma unroll
    for (int ks = 0; ks < 4; ks++) {
        int row = ks * 16 + bRowL;
#pragma unroll
        for (int nbp = 0; nbp < 2; nbp++)
            bOff[ks][nbp] = (uint32_t)(row * 256 + (((nq * 4 + nbp * 2 + hi) ^ (row & 7)) << 4));
    }
    const int pwChunk = lane >> 2;
    const int pwByte  = (lane & 3) * 4;

    issueA(0); issueH(0); cp_commit();
    issueA(1);            cp_commit();

    for (int t = 0; t < T_TILES; t++) {
        cp_wait1();
        __syncwarp();

        const float* sAt = (const float*)(smem + OFF_SA + (uint32_t)(t % 3) * SA_STRIDE);
        const uint32_t spW = spBase + (uint32_t)(t & 1) * SP_STRIDE;
        float2 f2v = *(const float2*)(&g_f2[b * NN + t * 64 + 2 * lane]);
#pragma unroll
        for (int r = 0; r < 4; r++) {
            int i = w * 4 + r;
            float2 av = ((const float2*)(sAt + i * 64))[lane];
            float s0 = rf1[r] + f2v.x;
            s0 = fmaxf(s0, LEAK * s0);
            float p0 = (av.x > 0.f) ? __expf(s0) : 1.0f;
            float s1 = rf1[r] + f2v.y;
            s1 = fmaxf(s1, LEAK * s1);
            float p1 = (av.y > 0.f) ? __expf(s1) : 1.0f;
            zacc[r] += p0 + p1;
            __half2 ph = __floats2half2_rn(p0, p1);
            uint32_t addr = spW + (uint32_t)(i * 128 + ((pwChunk ^ (i & 7)) << 4) + pwByte);
            asm volatile("st.shared.b32 [%0], %1;" :: "r"(addr), "r"(*(uint32_t*)&ph));
        }

        issueH(t + 1); cp_commit();
        issueA(t + 2); cp_commit();

        __syncthreads();

        const uint32_t spB = spBase + (uint32_t)(t & 1) * SP_STRIDE;
        const uint32_t shB = shBase + (uint32_t)(t % 3) * SH_STRIDE;
#pragma unroll
        for (int ks = 0; ks < 4; ks++) {
            uint32_t a0, a1, a2, a3;
            ldm_x4(a0, a1, a2, a3, spB + aOff[ks]);
#pragma unroll
            for (int nbp = 0; nbp < 2; nbp++) {
                uint32_t b0, b1, b2, b3;
                ldm_x4_t(b0, b1, b2, b3, shB + bOff[ks][nbp]);
                mma16816(acc[nbp * 2],     a0, a1, a2, a3, b0, b1);
                mma16816(acc[nbp * 2 + 1], a0, a1, a2, a3, b2, b3);
            }
        }
    }

#pragma unroll
    for (int r = 0; r < 4; r++) {
        float z = zacc[r];
#pragma unroll
        for (int off = 16; off; off >>= 1) z += __shfl_xor_sync(0xffffffffu, z, off);
        if (lane == 0) sZ[w * 4 + r] = z;
    }
    __syncthreads();

    const int gid = lane >> 2;
    const int tig = lane & 3;
    const float inv0 = 1.f / sZ[mb * 16 + gid];
    const float inv1 = 1.f / sZ[mb * 16 + gid + 8];
    const size_t base0 = ((size_t)b * NN + i0 + mb * 16 + gid) * DD;
    const size_t base1 = base0 + (size_t)8 * DD;
#pragma unroll
    for (int nb = 0; nb < 4; nb++) {
        int col = nq * 32 + nb * 8 + tig * 2;
        float2 v0 = make_float2(acc[nb][0] * inv0, acc[nb][1] * inv0);
        float2 v1 = make_float2(acc[nb][2] * inv1, acc[nb][3] * inv1);
        *(float2*)(out + base0 + col) = v0;
        *(float2*)(out + base1 + col) = v1;
    }
}

// ---------------------------------------------------------------------------
extern "C" void kernel_launch(void* const* d_in, const int* in_sizes, int n_in,
                              void* d_out, int out_size)
{
    (void)in_sizes; (void)n_in; (void)out_size;
    const float* A  = (const float*)d_in[0];   // [8, 2048, 2048]
    const float* H  = (const float*)d_in[1];   // [8, 2048, 256]
    const float* W  = (const float*)d_in[2];   // [256, 128]
    const float* a1 = (const float*)d_in[3];   // [128, 1]
    const float* a2 = (const float*)d_in[4];   // [128, 1]
    float* out = (float*)d_out;                // [8, 2048, 128] fp32

    cudaFuncSetAttribute(proj_kernel,
                         cudaFuncAttributeMaxDynamicSharedMemorySize, PJ_SMEM);
    proj_kernel<<<(BB * NN) / 64, 512, PJ_SMEM>>>(H, W, a1, a2);

    cudaFuncSetAttribute(gat_main_kernel,
                         cudaFuncAttributeMaxDynamicSharedMemorySize, SMEM_MAIN);
    dim3 grid(NN / 64, BB);
    gat_main_kernel<<<grid, 512, SMEM_MAIN>>>(A, out);
}

// round 15
// speedup vs baseline: 1.0255x; 1.0255x over previous
#include <cuda_runtime.h>
#include <cuda_fp16.h>
#include <cstdint>

#define BB   8
#define NN   2048
#define FIN  256
#define DD   128
#define LEAK 0.2f

// Scratch (device globals — no allocation in kernel_launch)
__device__ __half g_Hh[BB * NN * DD];   // H_ in fp16, [16384, 128]
__device__ float  g_f1[BB * NN];
__device__ float  g_f2[BB * NN];

// ---------------------------------------------------------------------------
// PTX helpers
// ---------------------------------------------------------------------------
__device__ __forceinline__ void cp_async16(uint32_t smem_addr, const void* gptr)
{
    asm volatile("cp.async.cg.shared.global [%0], [%1], 16;"
                 :: "r"(smem_addr), "l"(gptr));
}
__device__ __forceinline__ void cp_commit() { asm volatile("cp.async.commit_group;"); }
__device__ __forceinline__ void cp_wait1()  { asm volatile("cp.async.wait_group 1;"); }

__device__ __forceinline__ void ldm_x4(uint32_t& r0, uint32_t& r1, uint32_t& r2, uint32_t& r3,
                                       uint32_t addr)
{
    asm volatile("ldmatrix.sync.aligned.m8n8.x4.shared.b16 {%0,%1,%2,%3}, [%4];"
                 : "=r"(r0), "=r"(r1), "=r"(r2), "=r"(r3)
                 : "r"(addr));
}
__device__ __forceinline__ void ldm_x4_t(uint32_t& r0, uint32_t& r1, uint32_t& r2, uint32_t& r3,
                                         uint32_t addr)
{
    asm volatile("ldmatrix.sync.aligned.m8n8.x4.trans.shared.b16 {%0,%1,%2,%3}, [%4];"
                 : "=r"(r0), "=r"(r1), "=r"(r2), "=r"(r3)
                 : "r"(addr));
}
__device__ __forceinline__ void mma16816(float* c, uint32_t a0, uint32_t a1, uint32_t a2,
                                         uint32_t a3, uint32_t b0, uint32_t b1)
{
    asm volatile(
        "mma.sync.aligned.m16n8k16.row.col.f32.f16.f16.f32 "
        "{%0,%1,%2,%3}, {%4,%5,%6,%7}, {%8,%9}, {%0,%1,%2,%3};"
        : "+f"(c[0]), "+f"(c[1]), "+f"(c[2]), "+f"(c[3])
        : "r"(a0), "r"(a1), "r"(a2), "r"(a3), "r"(b0), "r"(b1));
}

__device__ __forceinline__ void split2(float x, float y, uint32_t& hi, uint32_t& lo)
{
    __half hx = __float2half_rn(x), hy = __float2half_rn(y);
    __half2 h = __halves2half2(hx, hy);
    __half2 l = __floats2half2_rn(x - __half2float(hx), y - __half2float(hy));
    hi = *(uint32_t*)&h;
    lo = *(uint32_t*)&l;
}

// ---------------------------------------------------------------------------
// Kernel 1 (v2): H_ = H @ W via fp16 tensor cores with 3-term hi/lo split
// (fp32-accurate: Hhi*Whi + Hhi*Wlo + Hlo*Whi, fp32 accumulate).
// CTA = 64 rows, 512 threads (16 warps: mq=w>>2 m16-band, nq=w&3 n32-slice),
// grid 256. K loop: 8 chunks of k32, reg-prefetch 1 ahead, 1 barrier/iter.
// Epilogue: fp16 H_ -> g_Hh, fused f1/f2 row-dots -> g_f1/g_f2.
// smem: hAhi[2][64][32] 8K | hAlo 8K | hWhi[2][32][128] 16K | hWlo 16K |
//       sPart1/2 2K  => 51200 B
// ---------------------------------------------------------------------------
#define PJ_OAHI 0u
#define PJ_OALO 8192u
#define PJ_OWHI 16384u
#define PJ_OWLO 32768u
#define PJ_OPRT 49152u
#define PJ_SMEM 51200

__global__ __launch_bounds__(512, 2) void proj_kernel(
    const float* __restrict__ H, const float* __restrict__ W,
    const float* __restrict__ a1, const float* __restrict__ a2)
{
    extern __shared__ char sm[];
    const uint32_t base = (uint32_t)__cvta_generic_to_shared(sm);
    float* sPart1 = (float*)(sm + PJ_OPRT);           // [64][4]
    float* sPart2 = (float*)(sm + PJ_OPRT + 1024);    // [64][4]

    const int tid  = threadIdx.x;
    const int lane = tid & 31;
    const int w    = tid >> 5;
    const int row0 = blockIdx.x * 64;                 // flat row base (0..16383)

    // load mappings
    const int hRow = tid >> 2,  hSeg = tid & 3;       // tid<256: H rows 0..63
    const int wRow = tid >> 4,  wSeg = tid & 15;      // W k-rows 0..31

    const uint32_t stAoff = (uint32_t)(hRow * 64 + ((hSeg ^ ((hRow >> 1) & 3)) << 4));
    const uint32_t stWoff = (uint32_t)(wRow * 256 + ((wSeg ^ (wRow & 7)) << 4));

    float4 ha0, ha1, wa0, wa1;
    auto loadH = [&](int kc) {
        const float4* p = (const float4*)(H + (size_t)(row0 + hRow) * FIN + kc * 32 + hSeg * 8);
        ha0 = p[0]; ha1 = p[1];
    };
    auto loadW = [&](int kc) {
        const float4* p = (const float4*)(W + (size_t)(kc * 32 + wRow) * DD + wSeg * 8);
        wa0 = p[0]; wa1 = p[1];
    };

    // mma addressing
    const int mq = w >> 2;              // 0..3 : rows mq*16..mq*16+15
    const int nq = w & 3;               // 0..3 : cols nq*32..nq*32+31
    const int l15 = lane & 15;
    const int hi  = lane >> 4;
    uint32_t aOff[2], bOff[2][2];
#pragma unroll
    for (int ksel = 0; ksel < 2; ksel++) {
        int arow = mq * 16 + l15;
        aOff[ksel] = (uint32_t)(arow * 64 + (((ksel * 2 + hi) ^ ((arow >> 1) & 3)) << 4));
        int brow = ksel * 16 + l15;
#pragma unroll
        for (int ns = 0; ns < 2; ns++)
            bOff[ksel][ns] = (uint32_t)(brow * 256 +
                (((nq * 4 + ns * 2 + hi) ^ (brow & 7)) << 4));
    }

    float acc[4][4];
#pragma unroll
    for (int f = 0; f < 4; f++)
#pragma unroll
        for (int c = 0; c < 4; c++) acc[f][c] = 0.f;

    if (tid < 256) loadH(0);
    loadW(0);

    for (int kc = 0; kc < 8; kc++) {
        const uint32_t abuf = (uint32_t)(kc & 1) * 4096u;
        const uint32_t wbuf = (uint32_t)(kc & 1) * 8192u;

        // convert & store hi/lo fp16 (generic-pointer 16B stores)
        if (tid < 256) {
            uint32_t h0, l0, h1, l1, h2, l2, h3, l3;
            split2(ha0.x, ha0.y, h0, l0); split2(ha0.z, ha0.w, h1, l1);
            split2(ha1.x, ha1.y, h2, l2); split2(ha1.z, ha1.w, h3, l3);
            *(uint4*)(sm + PJ_OAHI + abuf + stAoff) = make_uint4(h0, h1, h2, h3);
            *(uint4*)(sm + PJ_OALO + abuf + stAoff) = make_uint4(l0, l1, l2, l3);
        }
        {
            uint32_t h0, l0, h1, l1, h2, l2, h3, l3;
            split2(wa0.x, wa0.y, h0, l0); split2(wa0.z, wa0.w, h1, l1);
            split2(wa1.x, wa1.y, h2, l2); split2(wa1.z, wa1.w, h3, l3);
            *(uint4*)(sm + PJ_OWHI + wbuf + stWoff) = make_uint4(h0, h1, h2, h3);
            *(uint4*)(sm + PJ_OWLO + wbuf + stWoff) = make_uint4(l0, l1, l2, l3);
        }
        if (kc < 7) {
            if (tid < 256) loadH(kc + 1);
            loadW(kc + 1);
        }
        __syncthreads();

        // 3-split MMA on buf[kc&1]
        const uint32_t ahiB = base + PJ_OAHI + abuf;
        const uint32_t aloB = base + PJ_OALO + abuf;
        const uint32_t whiB = base + PJ_OWHI + wbuf;
        const uint32_t wloB = base + PJ_OWLO + wbuf;
#pragma unroll
        for (int ksel = 0; ksel < 2; ksel++) {
            uint32_t ah0, ah1, ah2, ah3, al0, al1, al2, al3;
            ldm_x4(ah0, ah1, ah2, ah3, ahiB + aOff[ksel]);
            ldm_x4(al0, al1, al2, al3, aloB + aOff[ksel]);
#pragma unroll
            for (int ns = 0; ns < 2; ns++) {
                uint32_t bh0, bh1, bh2, bh3, bl0, bl1, bl2, bl3;
                ldm_x4_t(bh0, bh1, bh2, bh3, whiB + bOff[ksel][ns]);
                ldm_x4_t(bl0, bl1, bl2, bl3, wloB + bOff[ksel][ns]);
                mma16816(acc[ns * 2 + 0], ah0, ah1, ah2, ah3, bh0, bh1);
                mma16816(acc[ns * 2 + 1], ah0, ah1, ah2, ah3, bh2, bh3);
                mma16816(acc[ns * 2 + 0], ah0, ah1, ah2, ah3, bl0, bl1);
                mma16816(acc[ns * 2 + 1], ah0, ah1, ah2, ah3, bl2, bl3);
                mma16816(acc[ns * 2 + 0], al0, al1, al2, al3, bh0, bh1);
                mma16816(acc[ns * 2 + 1], al0, al1, al2, al3, bh2, bh3);
            }
        }
    }

    // ---- epilogue ----
    const int gid = lane >> 2;
    const int tig = lane & 3;

    // f1/f2 partials over this lane's 8 columns
    float p1[2] = {0.f, 0.f}, p2[2] = {0.f, 0.f};
#pragma unroll
    for (int f = 0; f < 4; f++) {
        int col = nq * 32 + (f >> 1) * 16 + (f & 1) * 8 + tig * 2;
        float a1x = a1[col], a1y = a1[col + 1];
        float a2x = a2[col], a2y = a2[col + 1];
        p1[0] += acc[f][0] * a1x + acc[f][1] * a1y;
        p1[1] += acc[f][2] * a1x + acc[f][3] * a1y;
        p2[0] += acc[f][0] * a2x + acc[f][1] * a2y;
        p2[1] += acc[f][2] * a2x + acc[f][3] * a2y;
    }
#pragma unroll
    for (int off = 1; off <= 2; off <<= 1) {
#pragma unroll
        for (int rh = 0; rh < 2; rh++) {
            p1[rh] += __shfl_xor_sync(0xffffffffu, p1[rh], off);
            p2[rh] += __shfl_xor_sync(0xffffffffu, p2[rh], off);
        }
    }
    if (tig == 0) {
#pragma unroll
        for (int rh = 0; rh < 2; rh++) {
            int r = mq * 16 + rh * 8 + gid;
            sPart1[r * 4 + nq] = p1[rh];
            sPart2[r * 4 + nq] = p2[rh];
        }
    }

    // fp16 H_ store
#pragma unroll
    for (int rh = 0; rh < 2; rh++) {
        size_t grow = (size_t)(row0 + mq * 16 + rh * 8 + gid) * DD;
#pragma unroll
        for (int f = 0; f < 4; f++) {
            int col = nq * 32 + (f >> 1) * 16 + (f & 1) * 8 + tig * 2;
            __half2 hv = __floats2half2_rn(acc[f][rh * 2 + 0], acc[f][rh * 2 + 1]);
            *(uint32_t*)(&g_Hh[grow + col]) = *(uint32_t*)&hv;
        }
    }
    __syncthreads();

    if (tid < 64) {
        float s1 = sPart1[tid * 4] + sPart1[tid * 4 + 1] + sPart1[tid * 4 + 2] + sPart1[tid * 4 + 3];
        float s2 = sPart2[tid * 4] + sPart2[tid * 4 + 1] + sPart2[tid * 4 + 2] + sPart2[tid * 4 + 3];
        g_f1[row0 + tid] = s1;
        g_f2[row0 + tid] = s2;
    }
}

// ---------------------------------------------------------------------------
// Kernel 2: fused attention — EXACT R7 version (benched 64.4 us).
// ---------------------------------------------------------------------------
#define T_TILES   (NN / 64)
#define SA_STRIDE 16384u
#define SH_STRIDE 16384u
#define SP_STRIDE 8192u
#define OFF_SA    0u
#define OFF_SH    49152u
#define OFF_SP    98304u
#define OFF_SZ    114688u
#define SMEM_MAIN 114944

__global__ __launch_bounds__(512, 2) void gat_main_kernel(
    const float* __restrict__ A, float* __restrict__ out)
{
    extern __shared__ char smem[];
    const uint32_t smBase = (uint32_t)__cvta_generic_to_shared(smem);
    const uint32_t saBase = smBase + OFF_SA;
    const uint32_t shBase = smBase + OFF_SH;
    const uint32_t spBase = smBase + OFF_SP;
    float* sZ = (float*)(smem + OFF_SZ);

    const int tid  = threadIdx.x;
    const int lane = tid & 31;
    const int w    = tid >> 5;          // 0..15
    const int b    = blockIdx.y;
    const int i0   = blockIdx.x * 64;

    const float*  Ab  = A + (size_t)b * NN * NN;
    const __half* Hhb = g_Hh + (size_t)b * NN * DD;

    // A(t): WARP-SELF copy of the 4 rows this warp exp-reads.
    const int aRowSelf = 4 * w + (lane >> 4);
    const int aChunk   = lane & 15;
    auto issueA = [&](int t) {
        if (t >= T_TILES) return;
        const uint32_t dbuf = saBase + (uint32_t)(t % 3) * SA_STRIDE;
        const int j0 = t * 64;
#pragma unroll
        for (int p = 0; p < 2; p++) {
            int row = aRowSelf + p * 2;
            cp_async16(dbuf + (uint32_t)(row * 256 + aChunk * 16),
                       Ab + (size_t)(i0 + row) * NN + j0 + aChunk * 4);
        }
    };
    // H(t): spread copy, consumed post-barrier. XOR-chunk swizzle.
    const int ldRow = tid >> 4;
    const int ldC16 = tid & 15;
    auto issueH = [&](int t) {
        if (t >= T_TILES) return;
        const uint32_t dbuf = shBase + (uint32_t)(t % 3) * SH_STRIDE;
        const int j0 = t * 64;
#pragma unroll
        for (int p = 0; p < 2; p++) {
            int row = ldRow + p * 32;
            int sw = ldC16 ^ (row & 7);
            cp_async16(dbuf + (uint32_t)(row * 256 + sw * 16),
                       Hhb + (size_t)(j0 + row) * DD + ldC16 * 8);
        }
    };

    float rf1[4];
#pragma unroll
    for (int r = 0; r < 4; r++) rf1[r] = g_f1[b * NN + i0 + w * 4 + r];

    float zacc[4] = {0.f, 0.f, 0.f, 0.f};
    float acc[4][4];
#pragma unroll
    for (int nb = 0; nb < 4; nb++)
#pragma unroll
        for (int c = 0; c < 4; c++) acc[nb][c] = 0.f;

    const int mb = w & 3;
    const int nq = w >> 2;

    const int aRow  = mb * 16 + (lane & 15);
    const int bRowL = lane & 15;
    const int hi    = lane >> 4;
    uint32_t aOff[4];
#pragma unroll
    for (int ks = 0; ks < 4; ks++)
        aOff[ks] = (uint32_t)(aRow * 128 + (((ks * 2 + hi) ^ (aRow & 7)) << 4));
    uint32_t bOff[4][2];
#pragma unroll
    for (int ks = 0; ks < 4; ks++) {
        int row = ks * 16 + bRowL;
#pragma unroll
        for (int nbp = 0; nbp < 2; nbp++)
            bOff[ks][nbp] = (uint32_t)(row * 256 + (((nq * 4 + nbp * 2 + hi) ^ (row & 7)) << 4));
    }
    const int pwChunk = lane >> 2;
    const int pwByte  = (lane & 3) * 4;

    issueA(0); issueH(0); cp_commit();
    issueA(1);            cp_commit();

    for (int t = 0; t < T_TILES; t++) {
        cp_wait1();
        __syncwarp();

        const float* sAt = (const float*)(smem + OFF_SA + (uint32_t)(t % 3) * SA_STRIDE);
        const uint32_t spW = spBase + (uint32_t)(t & 1) * SP_STRIDE;
        float2 f2v = *(const float2*)(&g_f2[b * NN + t * 64 + 2 * lane]);
#pragma unroll
        for (int r = 0; r < 4; r++) {
            int i = w * 4 + r;
            float2 av = ((const float2*)(sAt + i * 64))[lane];
            float s0 = rf1[r] + f2v.x;
            s0 = fmaxf(s0, LEAK * s0);
            float p0 = (av.x > 0.f) ? __expf(s0) : 1.0f;
            float s1 = rf1[r] + f2v.y;
            s1 = fmaxf(s1, LEAK * s1);
            float p1 = (av.y > 0.f) ? __expf(s1) : 1.0f;
            zacc[r] += p0 + p1;
            __half2 ph = __floats2half2_rn(p0, p1);
            uint32_t addr = spW + (uint32_t)(i * 128 + ((pwChunk ^ (i & 7)) << 4) + pwByte);
            asm volatile("st.shared.b32 [%0], %1;" :: "r"(addr), "r"(*(uint32_t*)&ph));
        }

        issueH(t + 1); cp_commit();
        issueA(t + 2); cp_commit();

        __syncthreads();

        const uint32_t spB = spBase + (uint32_t)(t & 1) * SP_STRIDE;
        const uint32_t shB = shBase + (uint32_t)(t % 3) * SH_STRIDE;
#pragma unroll
        for (int ks = 0; ks < 4; ks++) {
            uint32_t a0, a1, a2, a3;
            ldm_x4(a0, a1, a2, a3, spB + aOff[ks]);
#pragma unroll
            for (int nbp = 0; nbp < 2; nbp++) {
                uint32_t b0, b1, b2, b3;
                ldm_x4_t(b0, b1, b2, b3, shB + bOff[ks][nbp]);
                mma16816(acc[nbp * 2],     a0, a1, a2, a3, b0, b1);
                mma16816(acc[nbp * 2 + 1], a0, a1, a2, a3, b2, b3);
            }
        }
    }

#pragma unroll
    for (int r = 0; r < 4; r++) {
        float z = zacc[r];
#pragma unroll
        for (int off = 16; off; off >>= 1) z += __shfl_xor_sync(0xffffffffu, z, off);
        if (lane == 0) sZ[w * 4 + r] = z;
    }
    __syncthreads();

    const int gid = lane >> 2;
    const int tig = lane & 3;
    const float inv0 = 1.f / sZ[mb * 16 + gid];
    const float inv1 = 1.f / sZ[mb * 16 + gid + 8];
    const size_t base0 = ((size_t)b * NN + i0 + mb * 16 + gid) * DD;
    const size_t base1 = base0 + (size_t)8 * DD;
#pragma unroll
    for (int nb = 0; nb < 4; nb++) {
        int col = nq * 32 + nb * 8 + tig * 2;
        float2 v0 = make_float2(acc[nb][0] * inv0, acc[nb][1] * inv0);
        float2 v1 = make_float2(acc[nb][2] * inv1, acc[nb][3] * inv1);
        *(float2*)(out + base0 + col) = v0;
        *(float2*)(out + base1 + col) = v1;
    }
}

// ---------------------------------------------------------------------------
extern "C" void kernel_launch(void* const* d_in, const int* in_sizes, int n_in,
                              void* d_out, int out_size)
{
    (void)in_sizes; (void)n_in; (void)out_size;
    const float* A  = (const float*)d_in[0];   // [8, 2048, 2048]
    const float* H  = (const float*)d_in[1];   // [8, 2048, 256]
    const float* W  = (const float*)d_in[2];   // [256, 128]
    const float* a1 = (const float*)d_in[3];   // [128, 1]
    const float* a2 = (const float*)d_in[4];   // [128, 1]
    float* out = (float*)d_out;                // [8, 2048, 128] fp32

    cudaFuncSetAttribute(proj_kernel,
                         cudaFuncAttributeMaxDynamicSharedMemorySize, PJ_SMEM);
    proj_kernel<<<(BB * NN) / 64, 512, PJ_SMEM>>>(H, W, a1, a2);

    cudaFuncSetAttribute(gat_main_kernel,
                         cudaFuncAttributeMaxDynamicSharedMemorySize, SMEM_MAIN);
    dim3 grid(NN / 64, BB);
    gat_main_kernel<<<grid, 512, SMEM_MAIN>>>(A, out);
}